// round 15
// baseline (speedup 1.0000x reference)
#include <cuda_runtime.h>
#include <stdint.h>

#define N_NODES 100000
#define E_EDGES 1600000
#define HID 64

// ---------------- scratch (no allocation allowed) ----------------
__device__ float g_bufA[N_NODES * HID];        // dinv-scaled GEMM out
__device__ float g_bufB[N_NODES * HID];        // layer output h
__device__ float g_dinv[N_NODES];
__device__ int   g_cnt[N_NODES];               // per-dst edge counts
__device__ int   g_off[N_NODES];               // CSR range starts (unordered alloc)
__device__ int   g_cur[N_NODES];               // fill cursors (init from off)
__device__ int   g_csr[E_EDGES];               // src indices grouped by dst
__device__ unsigned int g_total;               // bump allocator
__device__ int   g_is64;                       // 1 if edge_index is int64

__device__ __forceinline__ float lrelu1(float v) {
    return fmaxf(v, 0.f) + 0.01f * fminf(v, 0.f);
}

// ---------------- dtype detect (block 0) + zero cnt (blocks 1..) ----------
__global__ void k_detect_zero(const unsigned int* __restrict__ u32buf,
                              int* __restrict__ cnt, int n) {
    if (blockIdx.x == 0) {
        __shared__ unsigned int s_or[256];
        unsigned int acc = 0;
        for (int i = threadIdx.x; i < 2048; i += 256)
            acc |= u32buf[2 * i + 1];          // hi word of candidate int64 #i
        s_or[threadIdx.x] = acc;
        __syncthreads();
        for (int s = 128; s > 0; s >>= 1) {
            if (threadIdx.x < s) s_or[threadIdx.x] |= s_or[threadIdx.x + s];
            __syncthreads();
        }
        if (threadIdx.x == 0) {
            g_is64 = (s_or[0] == 0) ? 1 : 0;
            g_total = 0u;                      // reset bump allocator
        }
    } else {
        int i = (blockIdx.x - 1) * blockDim.x + threadIdx.x;
        if (i < n) cnt[i] = 0;
    }
}

__device__ __forceinline__ int load_idx(const unsigned int* u32buf, long long elem, int is64, int n) {
    unsigned int v = is64 ? u32buf[2 * elem] : u32buf[elem];
    int iv = (int)v;
    return min(max(iv, 0), n - 1);
}

// ---------------- fused: GEMM layer-1 (unscaled) || count in-degrees -------
// Blocks [0, gemmBlocks): row-per-thread GEMM (128 thr). Blocks after: count.
__global__ __launch_bounds__(128)
void k_gemm_count(const float* __restrict__ in, const float* __restrict__ W,
                  float* __restrict__ out,
                  const unsigned int* __restrict__ ei, int* __restrict__ cnt,
                  int n, int E, int gemmBlocks) {
    if ((int)blockIdx.x >= gemmBlocks) {
        // ---- count part ----
        int e = ((int)blockIdx.x - gemmBlocks) * 128 + threadIdx.x;
        if (e < E) {
            int is64 = g_is64;
            int d = load_idx(ei, (long long)E + e, is64, n);
            atomicAdd(cnt + d, 1);
        }
        return;
    }
    // ---- GEMM part (R11 body, no dinv scale) ----
    __shared__ float Ws[64 * 64];
    for (int i = threadIdx.x; i < 64 * 16; i += 128)
        ((float4*)Ws)[i] = ((const float4*)W)[i];
    __syncthreads();

    int row = blockIdx.x * 128 + threadIdx.x;
    if (row >= n) return;

    float acc[64];
#pragma unroll
    for (int j = 0; j < 64; j++) acc[j] = 0.f;

    const float4* inr = (const float4*)(in + (size_t)row * HID);

#pragma unroll 4
    for (int k4 = 0; k4 < 16; k4++) {
        float4 v = inr[k4];
        float av[4] = {v.x, v.y, v.z, v.w};
#pragma unroll
        for (int kk = 0; kk < 4; kk++) {
            const float* wrow = Ws + (k4 * 4 + kk) * 64;
#pragma unroll
            for (int j = 0; j < 64; j++)
                acc[j] = fmaf(av[kk], wrow[j], acc[j]);
        }
    }

    float4* outr = (float4*)(out + (size_t)row * HID);
#pragma unroll
    for (int j = 0; j < 16; j++)
        outr[j] = make_float4(acc[4 * j], acc[4 * j + 1], acc[4 * j + 2], acc[4 * j + 3]);
}

// ---------------- allocate CSR ranges (order-free bump alloc) + dinv -------
__global__ void k_alloc(const int* __restrict__ cnt, int* __restrict__ off,
                        int* __restrict__ cur, float* __restrict__ dinv, int n) {
    int i = blockIdx.x * blockDim.x + threadIdx.x;
    if (i < n) {
        int c = cnt[i];
        dinv[i] = rsqrtf(1.0f + (float)c);              // +1 self loop
        int o = (int)atomicAdd(&g_total, (unsigned int)c);   // warp-aggregated
        off[i] = o;
        cur[i] = o;
    }
}

// ---------------- fused: CSR fill || scale bufA by dinv --------------------
// Blocks [0, fillBlocks): fill. Blocks after: bufA[row] *= dinv[row] (float4).
__global__ __launch_bounds__(256)
void k_fill_scale(const unsigned int* __restrict__ ei,
                  int* __restrict__ cur, int* __restrict__ csr,
                  float* __restrict__ bufA, const float* __restrict__ dinv,
                  int E, int n, int fillBlocks) {
    if ((int)blockIdx.x < fillBlocks) {
        int e = blockIdx.x * 256 + threadIdx.x;
        if (e < E) {
            int is64 = g_is64;
            int s = load_idx(ei, e, is64, n);
            int d = load_idx(ei, (long long)E + e, is64, n);
            int pos = atomicAdd(cur + d, 1);
            csr[pos] = s;
        }
    } else {
        int gid = ((int)blockIdx.x - fillBlocks) * 256 + threadIdx.x;  // float4 slots
        if (gid < n * 16) {
            int node = gid >> 4;
            float di = __ldg(dinv + node);
            float4 v = ((const float4*)bufA)[gid];
            v.x *= di; v.y *= di; v.z *= di; v.w *= di;
            ((float4*)bufA)[gid] = v;
        }
    }
}

// ---------------- GEMM: out[n,64] = dinv[row] * (in[n,64] @ W[64,64]) ------
// (R11 row-per-thread body — frozen; layers 2,3)
__global__ __launch_bounds__(128)
void k_gemm64(const float* __restrict__ in, const float* __restrict__ W,
              const float* __restrict__ dinvv, float* __restrict__ out, int n) {
    __shared__ float Ws[64 * 64];
    for (int i = threadIdx.x; i < 64 * 16; i += blockDim.x)
        ((float4*)Ws)[i] = ((const float4*)W)[i];
    __syncthreads();

    int row = blockIdx.x * blockDim.x + threadIdx.x;
    if (row >= n) return;

    float acc[64];
#pragma unroll
    for (int j = 0; j < 64; j++) acc[j] = 0.f;

    const float4* inr = (const float4*)(in + (size_t)row * HID);

#pragma unroll 4
    for (int k4 = 0; k4 < 16; k4++) {
        float4 v = inr[k4];
        float av[4] = {v.x, v.y, v.z, v.w};
#pragma unroll
        for (int kk = 0; kk < 4; kk++) {
            const float* wrow = Ws + (k4 * 4 + kk) * 64;
#pragma unroll
            for (int j = 0; j < 64; j++)
                acc[j] = fmaf(av[kk], wrow[j], acc[j]);
        }
    }

    float di = __ldg(dinvv + row);
    float4* outr = (float4*)(out + (size_t)row * HID);
#pragma unroll
    for (int j = 0; j < 16; j++)
        outr[j] = make_float4(di * acc[4 * j], di * acc[4 * j + 1],
                              di * acc[4 * j + 2], di * acc[4 * j + 3]);
}

// ---------------- gather (R11 body — frozen) ----------------
__global__ __launch_bounds__(256)
void k_gather(const float* __restrict__ lin, const int* __restrict__ csr,
              const int* __restrict__ off, const int* __restrict__ cnt,
              const float* __restrict__ dinv,
              const float* __restrict__ bias, float* __restrict__ outp, int n) {
    int warp = (blockIdx.x * blockDim.x + threadIdx.x) >> 5;
    int lane = threadIdx.x & 31;
    if (warp >= n) return;
    int node = warp;

    int beg = __ldg(off + node);
    int end = beg + __ldg(cnt + node);

    const float2* lin2 = (const float2*)lin;
    float2 t = __ldg(lin2 + (size_t)node * 32 + lane);   // self term (pre-scaled)
    float tx = t.x, ty = t.y;

    int i = beg;
    for (; i + 2 <= end; i += 2) {
        int s0 = __ldg(csr + i);
        int s1 = __ldg(csr + i + 1);
        float2 v0 = __ldg(lin2 + (size_t)s0 * 32 + lane);
        float2 v1 = __ldg(lin2 + (size_t)s1 * 32 + lane);
        tx += v0.x; ty += v0.y;
        tx += v1.x; ty += v1.y;
    }
    if (i < end) {
        int s0 = __ldg(csr + i);
        float2 v0 = __ldg(lin2 + (size_t)s0 * 32 + lane);
        tx += v0.x; ty += v0.y;
    }

    float di = __ldg(dinv + node);
    float2 b = __ldg(((const float2*)bias) + lane);
    float2 o;
    o.x = lrelu1(fmaf(di, tx, b.x));
    o.y = lrelu1(fmaf(di, ty, b.y));
    ((float2*)outp)[(size_t)node * 32 + lane] = o;
}

// ---------------- launch ----------------
extern "C" void kernel_launch(void* const* d_in, const int* in_sizes, int n_in,
                              void* d_out, int out_size) {
    const float*        x  = (const float*)d_in[0];
    const unsigned int* ei = (const unsigned int*)d_in[1];
    const float*        W1 = (const float*)d_in[2];
    const float*        b1 = (const float*)d_in[3];
    const float*        W2 = (const float*)d_in[4];
    const float*        b2 = (const float*)d_in[5];
    const float*        W3 = (const float*)d_in[6];
    const float*        b3 = (const float*)d_in[7];
    float* out = (float*)d_out;

    const int n = in_sizes[0] / HID;        // 100000
    const int E = in_sizes[1] / 2;          // 1600000

    float* bufA;  cudaGetSymbolAddress((void**)&bufA, g_bufA);
    float* bufB;  cudaGetSymbolAddress((void**)&bufB, g_bufB);
    float* dinv;  cudaGetSymbolAddress((void**)&dinv, g_dinv);
    int*   cnt;   cudaGetSymbolAddress((void**)&cnt,  g_cnt);
    int*   off;   cudaGetSymbolAddress((void**)&off,  g_off);
    int*   cur;   cudaGetSymbolAddress((void**)&cur,  g_cur);
    int*   csr;   cudaGetSymbolAddress((void**)&csr,  g_csr);

    const int T = 256;
    int gn  = (n + T - 1) / T;
    int gRow = (n + 127) / 128;              // 782 GEMM blocks
    int gCnt = (E + 127) / 128;              // 12500 count blocks (128 thr)
    int gFill = (E + T - 1) / T;             // 6250 fill blocks
    int gScale = (n * 16 + T - 1) / T;       // 6250 scale blocks
    int gGat = (n * 32 + T - 1) / T;         // warp per node

    // build + layer-1 GEMM overlapped via block-range fusion
    k_detect_zero<<<1 + gn, T>>>(ei, cnt, n);
    k_gemm_count<<<gRow + gCnt, 128>>>(x, W1, bufA, ei, cnt, n, E, gRow);
    k_alloc<<<gn, T>>>(cnt, off, cur, dinv, n);
    k_fill_scale<<<gFill + gScale, T>>>(ei, cur, csr, bufA, dinv, E, n, gFill);

    // layer 1 gather
    k_gather<<<gGat, T>>>(bufA, csr, off, cnt, dinv, b1, bufB, n);
    // layer 2
    k_gemm64<<<gRow, 128>>>(bufB, W2, dinv, bufA, n);
    k_gather<<<gGat, T>>>(bufA, csr, off, cnt, dinv, b2, bufB, n);
    // layer 3 -> d_out directly (plain stores only)
    k_gemm64<<<gRow, 128>>>(bufB, W3, dinv, bufA, n);
    k_gather<<<gGat, T>>>(bufA, csr, off, cnt, dinv, b3, out, n);
}

// round 16
// speedup vs baseline: 1.0168x; 1.0168x over previous
#include <cuda_runtime.h>
#include <cuda_fp16.h>
#include <stdint.h>

#define N_NODES 100000
#define E_EDGES 1600000
#define HID 64

// ---------------- scratch (no allocation allowed) ----------------
__device__ uint2 g_bufA[N_NODES * 16];         // fp16 gather operand: 64 halves = 16 uint2/row
__device__ float g_bufB[N_NODES * HID];        // fp32 layer buffer
__device__ float g_dinv[N_NODES];
__device__ int   g_cnt[N_NODES];               // per-dst edge counts
__device__ int   g_off[N_NODES];               // CSR range starts (unordered alloc)
__device__ int   g_cur[N_NODES];               // fill cursors (init from off)
__device__ int   g_csr[E_EDGES];               // src indices grouped by dst
__device__ unsigned int g_total;               // bump allocator
__device__ int   g_is64;                       // 1 if edge_index is int64

__device__ __forceinline__ float lrelu1(float v) {
    return fmaxf(v, 0.f) + 0.01f * fminf(v, 0.f);
}

__device__ __forceinline__ unsigned int pack_h2(float a, float b) {
    __half2 h = __floats2half2_rn(a, b);
    return *reinterpret_cast<unsigned int*>(&h);
}
__device__ __forceinline__ float2 unpack_h2(unsigned int u) {
    __half2 h = *reinterpret_cast<__half2*>(&u);
    return __half22float2(h);
}

// ---------------- dtype detect (block 0) + zero cnt (blocks 1..) ----------
__global__ void k_detect_zero(const unsigned int* __restrict__ u32buf,
                              int* __restrict__ cnt, int n) {
    if (blockIdx.x == 0) {
        __shared__ unsigned int s_or[256];
        unsigned int acc = 0;
        for (int i = threadIdx.x; i < 2048; i += 256)
            acc |= u32buf[2 * i + 1];          // hi word of candidate int64 #i
        s_or[threadIdx.x] = acc;
        __syncthreads();
        for (int s = 128; s > 0; s >>= 1) {
            if (threadIdx.x < s) s_or[threadIdx.x] |= s_or[threadIdx.x + s];
            __syncthreads();
        }
        if (threadIdx.x == 0) {
            g_is64 = (s_or[0] == 0) ? 1 : 0;
            g_total = 0u;                      // reset bump allocator
        }
    } else {
        int i = (blockIdx.x - 1) * blockDim.x + threadIdx.x;
        if (i < n) cnt[i] = 0;
    }
}

__device__ __forceinline__ int load_idx(const unsigned int* u32buf, long long elem, int is64, int n) {
    unsigned int v = is64 ? u32buf[2 * elem] : u32buf[elem];
    int iv = (int)v;
    return min(max(iv, 0), n - 1);
}

// ---------------- fused: GEMM layer-1 (unscaled, fp32 out) || count --------
__global__ __launch_bounds__(128)
void k_gemm_count(const float* __restrict__ in, const float* __restrict__ W,
                  float* __restrict__ out,
                  const unsigned int* __restrict__ ei, int* __restrict__ cnt,
                  int n, int E, int gemmBlocks) {
    if ((int)blockIdx.x >= gemmBlocks) {
        int e = ((int)blockIdx.x - gemmBlocks) * 128 + threadIdx.x;
        if (e < E) {
            int is64 = g_is64;
            int d = load_idx(ei, (long long)E + e, is64, n);
            atomicAdd(cnt + d, 1);
        }
        return;
    }
    __shared__ float Ws[64 * 64];
    for (int i = threadIdx.x; i < 64 * 16; i += 128)
        ((float4*)Ws)[i] = ((const float4*)W)[i];
    __syncthreads();

    int row = blockIdx.x * 128 + threadIdx.x;
    if (row >= n) return;

    float acc[64];
#pragma unroll
    for (int j = 0; j < 64; j++) acc[j] = 0.f;

    const float4* inr = (const float4*)(in + (size_t)row * HID);

#pragma unroll 4
    for (int k4 = 0; k4 < 16; k4++) {
        float4 v = inr[k4];
        float av[4] = {v.x, v.y, v.z, v.w};
#pragma unroll
        for (int kk = 0; kk < 4; kk++) {
            const float* wrow = Ws + (k4 * 4 + kk) * 64;
#pragma unroll
            for (int j = 0; j < 64; j++)
                acc[j] = fmaf(av[kk], wrow[j], acc[j]);
        }
    }

    float4* outr = (float4*)(out + (size_t)row * HID);
#pragma unroll
    for (int j = 0; j < 16; j++)
        outr[j] = make_float4(acc[4 * j], acc[4 * j + 1], acc[4 * j + 2], acc[4 * j + 3]);
}

// ---------------- allocate CSR ranges (order-free bump alloc) + dinv -------
__global__ void k_alloc(const int* __restrict__ cnt, int* __restrict__ off,
                        int* __restrict__ cur, float* __restrict__ dinv, int n) {
    int i = blockIdx.x * blockDim.x + threadIdx.x;
    if (i < n) {
        int c = cnt[i];
        dinv[i] = rsqrtf(1.0f + (float)c);              // +1 self loop
        int o = (int)atomicAdd(&g_total, (unsigned int)c);   // warp-aggregated
        off[i] = o;
        cur[i] = o;
    }
}

// ---------------- fused: CSR fill || scale+convert bufB fp32 -> bufA fp16 --
__global__ __launch_bounds__(256)
void k_fill_scale(const unsigned int* __restrict__ ei,
                  int* __restrict__ cur, int* __restrict__ csr,
                  const float* __restrict__ src32, uint2* __restrict__ dst16,
                  const float* __restrict__ dinv,
                  int E, int n, int fillBlocks) {
    if ((int)blockIdx.x < fillBlocks) {
        int e = blockIdx.x * 256 + threadIdx.x;
        if (e < E) {
            int is64 = g_is64;
            int s = load_idx(ei, e, is64, n);
            int d = load_idx(ei, (long long)E + e, is64, n);
            int pos = atomicAdd(cur + d, 1);
            csr[pos] = s;
        }
    } else {
        int gid = ((int)blockIdx.x - fillBlocks) * 256 + threadIdx.x;  // float4 slots
        if (gid < n * 16) {
            int node = gid >> 4;
            float di = __ldg(dinv + node);
            float4 v = ((const float4*)src32)[gid];
            uint2 u;
            u.x = pack_h2(di * v.x, di * v.y);
            u.y = pack_h2(di * v.z, di * v.w);
            dst16[gid] = u;                    // uint2 slot gid = 4 halves
        }
    }
}

// ---------------- GEMM layers 2,3: dinv-scaled fp16 out --------------------
// (R11 body frozen; only the epilogue converts to half2)
__global__ __launch_bounds__(128)
void k_gemm64_h(const float* __restrict__ in, const float* __restrict__ W,
                const float* __restrict__ dinvv, uint2* __restrict__ out16, int n) {
    __shared__ float Ws[64 * 64];
    for (int i = threadIdx.x; i < 64 * 16; i += blockDim.x)
        ((float4*)Ws)[i] = ((const float4*)W)[i];
    __syncthreads();

    int row = blockIdx.x * blockDim.x + threadIdx.x;
    if (row >= n) return;

    float acc[64];
#pragma unroll
    for (int j = 0; j < 64; j++) acc[j] = 0.f;

    const float4* inr = (const float4*)(in + (size_t)row * HID);

#pragma unroll 4
    for (int k4 = 0; k4 < 16; k4++) {
        float4 v = inr[k4];
        float av[4] = {v.x, v.y, v.z, v.w};
#pragma unroll
        for (int kk = 0; kk < 4; kk++) {
            const float* wrow = Ws + (k4 * 4 + kk) * 64;
#pragma unroll
            for (int j = 0; j < 64; j++)
                acc[j] = fmaf(av[kk], wrow[j], acc[j]);
        }
    }

    float di = __ldg(dinvv + row);
    uint2* outr = out16 + (size_t)row * 16;     // 16 uint2 = 64 halves per row
#pragma unroll
    for (int j = 0; j < 16; j++) {
        uint2 u;
        u.x = pack_h2(di * acc[4 * j],     di * acc[4 * j + 1]);
        u.y = pack_h2(di * acc[4 * j + 2], di * acc[4 * j + 3]);
        outr[j] = u;
    }
}

// ---------------- gather: fp16 rows, fp32 accumulate ----------------------
// One warp per node; lane owns 2 feature columns (one half2/uint per row).
__global__ __launch_bounds__(256)
void k_gather(const unsigned int* __restrict__ lin16, const int* __restrict__ csr,
              const int* __restrict__ off, const int* __restrict__ cnt,
              const float* __restrict__ dinv,
              const float* __restrict__ bias, float* __restrict__ outp, int n) {
    int warp = (blockIdx.x * blockDim.x + threadIdx.x) >> 5;
    int lane = threadIdx.x & 31;
    if (warp >= n) return;
    int node = warp;

    int beg = __ldg(off + node);
    int end = beg + __ldg(cnt + node);

    float2 t = unpack_h2(__ldg(lin16 + (size_t)node * 32 + lane));  // self (pre-scaled)
    float tx = t.x, ty = t.y;

    int i = beg;
    for (; i + 2 <= end; i += 2) {
        int s0 = __ldg(csr + i);
        int s1 = __ldg(csr + i + 1);
        float2 v0 = unpack_h2(__ldg(lin16 + (size_t)s0 * 32 + lane));
        float2 v1 = unpack_h2(__ldg(lin16 + (size_t)s1 * 32 + lane));
        tx += v0.x; ty += v0.y;
        tx += v1.x; ty += v1.y;
    }
    if (i < end) {
        int s0 = __ldg(csr + i);
        float2 v0 = unpack_h2(__ldg(lin16 + (size_t)s0 * 32 + lane));
        tx += v0.x; ty += v0.y;
    }

    float di = __ldg(dinv + node);
    float2 b = __ldg(((const float2*)bias) + lane);
    float2 o;
    o.x = lrelu1(fmaf(di, tx, b.x));
    o.y = lrelu1(fmaf(di, ty, b.y));
    ((float2*)outp)[(size_t)node * 32 + lane] = o;
}

// ---------------- launch ----------------
extern "C" void kernel_launch(void* const* d_in, const int* in_sizes, int n_in,
                              void* d_out, int out_size) {
    const float*        x  = (const float*)d_in[0];
    const unsigned int* ei = (const unsigned int*)d_in[1];
    const float*        W1 = (const float*)d_in[2];
    const float*        b1 = (const float*)d_in[3];
    const float*        W2 = (const float*)d_in[4];
    const float*        b2 = (const float*)d_in[5];
    const float*        W3 = (const float*)d_in[6];
    const float*        b3 = (const float*)d_in[7];
    float* out = (float*)d_out;

    const int n = in_sizes[0] / HID;        // 100000
    const int E = in_sizes[1] / 2;          // 1600000

    uint2* bufA;  cudaGetSymbolAddress((void**)&bufA, g_bufA);
    float* bufB;  cudaGetSymbolAddress((void**)&bufB, g_bufB);
    float* dinv;  cudaGetSymbolAddress((void**)&dinv, g_dinv);
    int*   cnt;   cudaGetSymbolAddress((void**)&cnt,  g_cnt);
    int*   off;   cudaGetSymbolAddress((void**)&off,  g_off);
    int*   cur;   cudaGetSymbolAddress((void**)&cur,  g_cur);
    int*   csr;   cudaGetSymbolAddress((void**)&csr,  g_csr);

    const int T = 256;
    int gn  = (n + T - 1) / T;
    int gRow = (n + 127) / 128;              // 782 GEMM blocks
    int gCnt = (E + 127) / 128;              // count blocks
    int gFill = (E + T - 1) / T;             // 6250 fill blocks
    int gScale = (n * 16 + T - 1) / T;       // 6250 scale blocks
    int gGat = (n * 32 + T - 1) / T;         // warp per node

    // build + layer-1 GEMM overlapped
    k_detect_zero<<<1 + gn, T>>>(ei, cnt, n);
    k_gemm_count<<<gRow + gCnt, 128>>>(x, W1, bufB, ei, cnt, n, E, gRow);
    k_alloc<<<gn, T>>>(cnt, off, cur, dinv, n);
    k_fill_scale<<<gFill + gScale, T>>>(ei, cur, csr, bufB, bufA, dinv, E, n, gFill);

    // layer 1 gather (fp16 in, fp32 out)
    k_gather<<<gGat, T>>>((const unsigned int*)bufA, csr, off, cnt, dinv, b1, bufB, n);
    // layer 2
    k_gemm64_h<<<gRow, 128>>>(bufB, W2, dinv, bufA, n);
    k_gather<<<gGat, T>>>((const unsigned int*)bufA, csr, off, cnt, dinv, b2, bufB, n);
    // layer 3 -> d_out (fp32 plain stores)
    k_gemm64_h<<<gRow, 128>>>(bufB, W3, dinv, bufA, n);
    k_gather<<<gGat, T>>>((const unsigned int*)bufA, csr, off, cnt, dinv, b3, out, n);
}

// round 17
// speedup vs baseline: 1.0333x; 1.0162x over previous
#include <cuda_runtime.h>
#include <cuda_fp16.h>
#include <stdint.h>

#define N_NODES 100000
#define E_EDGES 1600000
#define CSR_CAP (E_EDGES + 4 * N_NODES)        // padded: per-node alloc rounded to 4
#define HID 64

// ---------------- scratch (no allocation allowed) ----------------
__device__ uint2 g_bufA[N_NODES * 16];         // fp16 gather operand: 64 halves = 16 uint2/row
__device__ float g_bufB[N_NODES * HID];        // fp32 layer buffer
__device__ float g_dinv[N_NODES];
__device__ int   g_cnt[N_NODES];               // per-dst edge counts
__device__ int   g_off[N_NODES];               // CSR range starts (unordered alloc, 4-aligned)
__device__ int   g_cur[N_NODES];               // fill cursors (init from off)
__device__ __align__(16) int g_csr[CSR_CAP];   // src indices grouped by dst
__device__ unsigned int g_total;               // bump allocator
__device__ int   g_is64;                       // 1 if edge_index is int64

__device__ __forceinline__ float lrelu1(float v) {
    return fmaxf(v, 0.f) + 0.01f * fminf(v, 0.f);
}

__device__ __forceinline__ unsigned int pack_h2(float a, float b) {
    __half2 h = __floats2half2_rn(a, b);
    return *reinterpret_cast<unsigned int*>(&h);
}
__device__ __forceinline__ float2 unpack_h2(unsigned int u) {
    __half2 h = *reinterpret_cast<__half2*>(&u);
    return __half22float2(h);
}

// ---------------- dtype detect (block 0) + zero cnt (blocks 1..) ----------
__global__ void k_detect_zero(const unsigned int* __restrict__ u32buf,
                              int* __restrict__ cnt, int n) {
    if (blockIdx.x == 0) {
        __shared__ unsigned int s_or[256];
        unsigned int acc = 0;
        for (int i = threadIdx.x; i < 2048; i += 256)
            acc |= u32buf[2 * i + 1];          // hi word of candidate int64 #i
        s_or[threadIdx.x] = acc;
        __syncthreads();
        for (int s = 128; s > 0; s >>= 1) {
            if (threadIdx.x < s) s_or[threadIdx.x] |= s_or[threadIdx.x + s];
            __syncthreads();
        }
        if (threadIdx.x == 0) {
            g_is64 = (s_or[0] == 0) ? 1 : 0;
            g_total = 0u;                      // reset bump allocator
        }
    } else {
        int i = (blockIdx.x - 1) * blockDim.x + threadIdx.x;
        if (i < n) cnt[i] = 0;
    }
}

__device__ __forceinline__ int load_idx(const unsigned int* u32buf, long long elem, int is64, int n) {
    unsigned int v = is64 ? u32buf[2 * elem] : u32buf[elem];
    int iv = (int)v;
    return min(max(iv, 0), n - 1);
}

// ---------------- fused: GEMM layer-1 (unscaled, fp32 out) || count --------
__global__ __launch_bounds__(128)
void k_gemm_count(const float* __restrict__ in, const float* __restrict__ W,
                  float* __restrict__ out,
                  const unsigned int* __restrict__ ei, int* __restrict__ cnt,
                  int n, int E, int gemmBlocks) {
    if ((int)blockIdx.x >= gemmBlocks) {
        int e = ((int)blockIdx.x - gemmBlocks) * 128 + threadIdx.x;
        if (e < E) {
            int is64 = g_is64;
            int d = load_idx(ei, (long long)E + e, is64, n);
            atomicAdd(cnt + d, 1);
        }
        return;
    }
    __shared__ float Ws[64 * 64];
    for (int i = threadIdx.x; i < 64 * 16; i += 128)
        ((float4*)Ws)[i] = ((const float4*)W)[i];
    __syncthreads();

    int row = blockIdx.x * 128 + threadIdx.x;
    if (row >= n) return;

    float acc[64];
#pragma unroll
    for (int j = 0; j < 64; j++) acc[j] = 0.f;

    const float4* inr = (const float4*)(in + (size_t)row * HID);

#pragma unroll 4
    for (int k4 = 0; k4 < 16; k4++) {
        float4 v = inr[k4];
        float av[4] = {v.x, v.y, v.z, v.w};
#pragma unroll
        for (int kk = 0; kk < 4; kk++) {
            const float* wrow = Ws + (k4 * 4 + kk) * 64;
#pragma unroll
            for (int j = 0; j < 64; j++)
                acc[j] = fmaf(av[kk], wrow[j], acc[j]);
        }
    }

    float4* outr = (float4*)(out + (size_t)row * HID);
#pragma unroll
    for (int j = 0; j < 16; j++)
        outr[j] = make_float4(acc[4 * j], acc[4 * j + 1], acc[4 * j + 2], acc[4 * j + 3]);
}

// ---------------- allocate CSR ranges (bump alloc, rounded to 4) + dinv ----
__global__ void k_alloc(const int* __restrict__ cnt, int* __restrict__ off,
                        int* __restrict__ cur, float* __restrict__ dinv, int n) {
    int i = blockIdx.x * blockDim.x + threadIdx.x;
    if (i < n) {
        int c = cnt[i];
        dinv[i] = rsqrtf(1.0f + (float)c);              // +1 self loop
        unsigned int c4 = (unsigned int)((c + 3) & ~3); // 4-aligned slot count
        int o = (int)atomicAdd(&g_total, c4);           // warp-aggregated
        off[i] = o;
        cur[i] = o;
    }
}

// ---------------- fused: CSR fill || scale+convert bufB fp32 -> bufA fp16 --
__global__ __launch_bounds__(256)
void k_fill_scale(const unsigned int* __restrict__ ei,
                  int* __restrict__ cur, int* __restrict__ csr,
                  const float* __restrict__ src32, uint2* __restrict__ dst16,
                  const float* __restrict__ dinv,
                  int E, int n, int fillBlocks) {
    if ((int)blockIdx.x < fillBlocks) {
        int e = blockIdx.x * 256 + threadIdx.x;
        if (e < E) {
            int is64 = g_is64;
            int s = load_idx(ei, e, is64, n);
            int d = load_idx(ei, (long long)E + e, is64, n);
            int pos = atomicAdd(cur + d, 1);
            csr[pos] = s;
        }
    } else {
        int gid = ((int)blockIdx.x - fillBlocks) * 256 + threadIdx.x;  // float4 slots
        if (gid < n * 16) {
            int node = gid >> 4;
            float di = __ldg(dinv + node);
            float4 v = ((const float4*)src32)[gid];
            uint2 u;
            u.x = pack_h2(di * v.x, di * v.y);
            u.y = pack_h2(di * v.z, di * v.w);
            dst16[gid] = u;
        }
    }
}

// ---------------- GEMM layers 2,3: dinv-scaled fp16 out --------------------
__global__ __launch_bounds__(128)
void k_gemm64_h(const float* __restrict__ in, const float* __restrict__ W,
                const float* __restrict__ dinvv, uint2* __restrict__ out16, int n) {
    __shared__ float Ws[64 * 64];
    for (int i = threadIdx.x; i < 64 * 16; i += blockDim.x)
        ((float4*)Ws)[i] = ((const float4*)W)[i];
    __syncthreads();

    int row = blockIdx.x * blockDim.x + threadIdx.x;
    if (row >= n) return;

    float acc[64];
#pragma unroll
    for (int j = 0; j < 64; j++) acc[j] = 0.f;

    const float4* inr = (const float4*)(in + (size_t)row * HID);

#pragma unroll 4
    for (int k4 = 0; k4 < 16; k4++) {
        float4 v = inr[k4];
        float av[4] = {v.x, v.y, v.z, v.w};
#pragma unroll
        for (int kk = 0; kk < 4; kk++) {
            const float* wrow = Ws + (k4 * 4 + kk) * 64;
#pragma unroll
            for (int j = 0; j < 64; j++)
                acc[j] = fmaf(av[kk], wrow[j], acc[j]);
        }
    }

    float di = __ldg(dinvv + row);
    uint2* outr = out16 + (size_t)row * 16;     // 16 uint2 = 64 halves per row
#pragma unroll
    for (int j = 0; j < 16; j++) {
        uint2 u;
        u.x = pack_h2(di * acc[4 * j],     di * acc[4 * j + 1]);
        u.y = pack_h2(di * acc[4 * j + 2], di * acc[4 * j + 3]);
        outr[j] = u;
    }
}

// ---------------- gather: fp16 rows, fp32 accumulate ----------------------
// One warp per node; lane owns 2 feature cols (one half2 per row).
// Edge indices fetched 4-at-a-time via one int4 broadcast LDG (beg 16B-aligned).
__global__ __launch_bounds__(256)
void k_gather(const unsigned int* __restrict__ lin16, const int* __restrict__ csr,
              const int* __restrict__ off, const int* __restrict__ cnt,
              const float* __restrict__ dinv,
              const float* __restrict__ bias, float* __restrict__ outp, int n) {
    int warp = (blockIdx.x * blockDim.x + threadIdx.x) >> 5;
    int lane = threadIdx.x & 31;
    if (warp >= n) return;
    int node = warp;

    int beg = __ldg(off + node);                 // 4-aligned
    int end = beg + __ldg(cnt + node);

    float2 t = unpack_h2(__ldg(lin16 + (size_t)node * 32 + lane));  // self (pre-scaled)
    float tx = t.x, ty = t.y;

    int i = beg;
    for (; i + 4 <= end; i += 4) {
        int4 q = __ldg((const int4*)(csr + i));  // 4 edges, one broadcast LDG
        float2 v0 = unpack_h2(__ldg(lin16 + (size_t)q.x * 32 + lane));
        float2 v1 = unpack_h2(__ldg(lin16 + (size_t)q.y * 32 + lane));
        float2 v2 = unpack_h2(__ldg(lin16 + (size_t)q.z * 32 + lane));
        float2 v3 = unpack_h2(__ldg(lin16 + (size_t)q.w * 32 + lane));
        tx += v0.x; ty += v0.y;
        tx += v1.x; ty += v1.y;
        tx += v2.x; ty += v2.y;
        tx += v3.x; ty += v3.y;
    }
    if (i < end) {                               // tail: <=3 edges, one int4 covers them
        int4 q = __ldg((const int4*)(csr + i));  // padded slots allocated, contents unused
        int rem = end - i;
        float2 v0 = unpack_h2(__ldg(lin16 + (size_t)q.x * 32 + lane));
        tx += v0.x; ty += v0.y;
        if (rem > 1) {
            float2 v1 = unpack_h2(__ldg(lin16 + (size_t)q.y * 32 + lane));
            tx += v1.x; ty += v1.y;
        }
        if (rem > 2) {
            float2 v2 = unpack_h2(__ldg(lin16 + (size_t)q.z * 32 + lane));
            tx += v2.x; ty += v2.y;
        }
    }

    float di = __ldg(dinv + node);
    float2 b = __ldg(((const float2*)bias) + lane);
    float2 o;
    o.x = lrelu1(fmaf(di, tx, b.x));
    o.y = lrelu1(fmaf(di, ty, b.y));
    ((float2*)outp)[(size_t)node * 32 + lane] = o;
}

// ---------------- launch ----------------
extern "C" void kernel_launch(void* const* d_in, const int* in_sizes, int n_in,
                              void* d_out, int out_size) {
    const float*        x  = (const float*)d_in[0];
    const unsigned int* ei = (const unsigned int*)d_in[1];
    const float*        W1 = (const float*)d_in[2];
    const float*        b1 = (const float*)d_in[3];
    const float*        W2 = (const float*)d_in[4];
    const float*        b2 = (const float*)d_in[5];
    const float*        W3 = (const float*)d_in[6];
    const float*        b3 = (const float*)d_in[7];
    float* out = (float*)d_out;

    const int n = in_sizes[0] / HID;        // 100000
    const int E = in_sizes[1] / 2;          // 1600000

    uint2* bufA;  cudaGetSymbolAddress((void**)&bufA, g_bufA);
    float* bufB;  cudaGetSymbolAddress((void**)&bufB, g_bufB);
    float* dinv;  cudaGetSymbolAddress((void**)&dinv, g_dinv);
    int*   cnt;   cudaGetSymbolAddress((void**)&cnt,  g_cnt);
    int*   off;   cudaGetSymbolAddress((void**)&off,  g_off);
    int*   cur;   cudaGetSymbolAddress((void**)&cur,  g_cur);
    int*   csr;   cudaGetSymbolAddress((void**)&csr,  g_csr);

    const int T = 256;
    int gn  = (n + T - 1) / T;
    int gRow = (n + 127) / 128;              // 782 GEMM blocks
    int gCnt = (E + 127) / 128;              // count blocks
    int gFill = (E + T - 1) / T;             // 6250 fill blocks
    int gScale = (n * 16 + T - 1) / T;       // 6250 scale blocks
    int gGat = (n * 32 + T - 1) / T;         // warp per node

    // build + layer-1 GEMM overlapped
    k_detect_zero<<<1 + gn, T>>>(ei, cnt, n);
    k_gemm_count<<<gRow + gCnt, 128>>>(x, W1, bufB, ei, cnt, n, E, gRow);
    k_alloc<<<gn, T>>>(cnt, off, cur, dinv, n);
    k_fill_scale<<<gFill + gScale, T>>>(ei, cur, csr, bufB, bufA, dinv, E, n, gFill);

    // layer 1 gather (fp16 in, fp32 out)
    k_gather<<<gGat, T>>>((const unsigned int*)bufA, csr, off, cnt, dinv, b1, bufB, n);
    // layer 2
    k_gemm64_h<<<gRow, 128>>>(bufB, W2, dinv, bufA, n);
    k_gather<<<gGat, T>>>((const unsigned int*)bufA, csr, off, cnt, dinv, b2, bufB, n);
    // layer 3 -> d_out (fp32 plain stores)
    k_gemm64_h<<<gRow, 128>>>(bufB, W3, dinv, bufA, n);
    k_gather<<<gGat, T>>>((const unsigned int*)bufA, csr, off, cnt, dinv, b3, out, n);
}